// round 9
// baseline (speedup 1.0000x reference)
#include <cuda_runtime.h>
#include <cuda_bf16.h>
#include <math.h>
#include <stdint.h>

// ---------------- problem constants ----------------
#define N_TOTAL   1000000
#define N_GATHER  200000
#define M_UPD     131072
#define MSG_DIM   512
#define DIM       256
#define G3        768
#define LN_EPS    1e-5f

// ---------------- scratch (static device globals: allocation-free) ----------------
// A operands stored WITHOUT hi duplication: [Ah | Al], row length 2K.
__device__ __nv_bfloat16 g_ax[(size_t)M_UPD * 2 * MSG_DIM];  // 268 MB
__device__ __nv_bfloat16 g_ah[(size_t)M_UPD * 2 * DIM];      // 134 MB
// B operands stored in full logical order: [Bh | Bl | Bh], row length 3K (tiny).
__device__ __nv_bfloat16 g_bx[(size_t)G3 * 3 * MSG_DIM];
__device__ __nv_bfloat16 g_bh[(size_t)G3 * 3 * DIM];
__device__ float g_gx[(size_t)M_UPD * G3];
__device__ float g_gh[(size_t)M_UPD * G3];
__device__ int   g_rid[M_UPD];

// ---------------- helpers ----------------
__device__ __forceinline__ uint32_t smem_u32(const void* p) {
    uint32_t a;
    asm("{ .reg .u64 t; cvta.to.shared.u64 t, %1; cvt.u32.u64 %0, t; }" : "=r"(a) : "l"(p));
    return a;
}
__device__ __forceinline__ void cpa16(uint32_t dst, const void* src) {
    asm volatile("cp.async.cg.shared.global [%0], [%1], 16;" :: "r"(dst), "l"(src) : "memory");
}
__device__ __forceinline__ void ldsm4(uint32_t* r, uint32_t addr) {
    asm volatile("ldmatrix.sync.aligned.m8n8.x4.shared.b16 {%0,%1,%2,%3}, [%4];"
                 : "=r"(r[0]), "=r"(r[1]), "=r"(r[2]), "=r"(r[3]) : "r"(addr));
}
__device__ __forceinline__ void mma16816(float* d, const uint32_t* a, uint32_t b0, uint32_t b1) {
    asm volatile("mma.sync.aligned.m16n8k16.row.col.f32.bf16.bf16.f32 "
                 "{%0,%1,%2,%3}, {%4,%5,%6,%7}, {%8,%9}, {%0,%1,%2,%3};"
                 : "+f"(d[0]), "+f"(d[1]), "+f"(d[2]), "+f"(d[3])
                 : "r"(a[0]), "r"(a[1]), "r"(a[2]), "r"(a[3]), "r"(b0), "r"(b1));
}
__device__ __forceinline__ float sigm(float x) { return 1.0f / (1.0f + expf(-x)); }

// ==================================================================================
// Conversion: X[rows,K] fp32 (optionally row-gathered) -> bf16 hi/lo.
//   bmode=0 (A operand): row = [hi | lo]          (length 2K)
//   bmode=1 (B operand): row = [hi | lo | hi]     (length 3K)
// GEMM pairs logical segments so sum = Ah*Bh + Ah*Bl + Al*Bh (Al*Bl dropped, ~4e-6).
// ==================================================================================
__global__ void conv_hilo(const float* __restrict__ src, const int* __restrict__ rowidx,
                          __nv_bfloat16* __restrict__ dst, int K, int bmode)
{
    const int q  = blockIdx.x * 256 + threadIdx.x;   // grid sized exactly: rows*K/4 threads
    const int kq = K >> 2;
    const int m  = q / kq;
    const int k  = (q - m * kq) << 2;

    const int srow = rowidx ? rowidx[m] : m;
    const float4 v = *(const float4*)(src + (size_t)srow * K + k);

    const __nv_bfloat16 h0 = __float2bfloat16(v.x);
    const __nv_bfloat16 h1 = __float2bfloat16(v.y);
    const __nv_bfloat16 h2 = __float2bfloat16(v.z);
    const __nv_bfloat16 h3 = __float2bfloat16(v.w);
    const __nv_bfloat16 l0 = __float2bfloat16(v.x - __bfloat162float(h0));
    const __nv_bfloat16 l1 = __float2bfloat16(v.y - __bfloat162float(h1));
    const __nv_bfloat16 l2 = __float2bfloat16(v.z - __bfloat162float(h2));
    const __nv_bfloat16 l3 = __float2bfloat16(v.w - __bfloat162float(h3));

    unsigned long long hq =  (unsigned long long)__bfloat16_as_ushort(h0)
                          | ((unsigned long long)__bfloat16_as_ushort(h1) << 16)
                          | ((unsigned long long)__bfloat16_as_ushort(h2) << 32)
                          | ((unsigned long long)__bfloat16_as_ushort(h3) << 48);
    unsigned long long lq =  (unsigned long long)__bfloat16_as_ushort(l0)
                          | ((unsigned long long)__bfloat16_as_ushort(l1) << 16)
                          | ((unsigned long long)__bfloat16_as_ushort(l2) << 32)
                          | ((unsigned long long)__bfloat16_as_ushort(l3) << 48);

    if (bmode == 0) {
        unsigned long long* drow = (unsigned long long*)(dst + (size_t)m * 2 * K);
        drow[k >> 2]           = hq;
        drow[(K + k) >> 2]     = lq;
    } else {
        unsigned long long* drow = (unsigned long long*)(dst + (size_t)m * 3 * K);
        drow[k >> 2]           = hq;
        drow[(K + k) >> 2]     = lq;
        drow[(2 * K + k) >> 2] = hq;
    }
}

// ==================================================================================
// HMMA GEMM: C[M,768] = A[M,2K](no-dup hi/lo) @ B[768,3K]^T + bias
// Logical K' = 3K traversed in 64-wide chunks; A chunk remapped (seg0,1->Ah, seg2->Al).
// bf16 mma.sync m16n8k16 (row.col, TN), fp32 accum.
// CTA tile 128x128x64, 8 warps (4M x 2N, warp tile 32x64), 2-stage cp.async ring.
// SMEM rows padded to 144B: conflict-free for cp.async STS.128 and LDSM phases.
// ==================================================================================
#define STAGES    2
#define ROWB      144u
#define STAGE_B   (128u * ROWB)            // 18432 B per matrix per stage
#define SMEM_DYN  (2 * STAGES * STAGE_B)   // 73728 B

__global__ __launch_bounds__(256, 2)
void hmma_gemm(const __nv_bfloat16* __restrict__ A, const __nv_bfloat16* __restrict__ B,
               const float* __restrict__ bias, float* __restrict__ C, int segsh)
{
    extern __shared__ char dsm[];
    __shared__ float sbias[128];

    const int tid = threadIdx.x, wid = tid >> 5, lane = tid & 31;
    const int Tn = blockIdx.x, Tm = blockIdx.y;
    const int segch   = 1 << segsh;        // 64-chunks per K segment (8 for K=512, 4 for K=256)
    const int nch     = 3 << segsh;        // logical chunks
    const int strideA = 128 << segsh;      // 2K elements
    const int strideB = 192 << segsh;      // 3K elements

    if (tid < 128) sbias[tid] = bias[Tn * 128 + tid];

    const uint32_t smA = smem_u32(dsm);
    const uint32_t smB = smA + STAGES * STAGE_B;

    // ---- cp.async mapping: thread covers row r, 64B half h (4x 16B chunks) ----
    const int r = tid >> 1, h = tid & 1;
    const __nv_bfloat16* aG = A + (size_t)(Tm * 128 + r) * strideA + h * 32;
    const __nv_bfloat16* bG = B + (size_t)(Tn * 128 + r) * strideB + h * 32;
    const uint32_t dA = smA + r * ROWB + h * 64;
    const uint32_t dB = smB + r * ROWB + h * 64;

#define ISSUE(kt)                                                                  \
    do { const int s_ = (kt) >> segsh, c_ = (kt) & (segch - 1);                    \
         const int ach_ = (s_ == 2) ? (segch + c_) : c_;                           \
         const uint32_t so_ = ((kt) & 1) * STAGE_B;                                \
         const __nv_bfloat16* ag_ = aG + ach_ * 64;                                \
         const __nv_bfloat16* bg_ = bG + (size_t)(kt) * 64;                        \
         cpa16(dA + so_,      ag_);      cpa16(dA + so_ + 16, ag_ + 8);            \
         cpa16(dA + so_ + 32, ag_ + 16); cpa16(dA + so_ + 48, ag_ + 24);           \
         cpa16(dB + so_,      bg_);      cpa16(dB + so_ + 16, bg_ + 8);            \
         cpa16(dB + so_ + 32, bg_ + 16); cpa16(dB + so_ + 48, bg_ + 24);           \
         asm volatile("cp.async.commit_group;" ::: "memory"); } while (0)

    // ---- ldmatrix per-lane base addresses (stage-relative byte offsets) ----
    const int wm = wid >> 1, wn = wid & 1;
    const int m0 = wm * 32,  n0 = wn * 64;
    const uint32_t aBase = smA + (m0 + (lane & 15)) * ROWB + (lane >> 4) * 16;
    const uint32_t bBase = smB + (n0 + (((lane >> 4) & 1) * 8) + (lane & 7)) * ROWB
                               + (((lane >> 3) & 1) * 16);

    float acc[2][8][4];
    #pragma unroll
    for (int mi = 0; mi < 2; ++mi)
        #pragma unroll
        for (int ni = 0; ni < 8; ++ni)
            #pragma unroll
            for (int j = 0; j < 4; ++j) acc[mi][ni][j] = 0.f;

    ISSUE(0); ISSUE(1);

    for (int kt = 0; kt < nch; ++kt) {
        if (kt + 1 < nch) asm volatile("cp.async.wait_group 1;" ::: "memory");
        else              asm volatile("cp.async.wait_group 0;" ::: "memory");
        __syncthreads();

        const uint32_t so = (kt & 1) * STAGE_B;
        #pragma unroll
        for (int k16 = 0; k16 < 4; ++k16) {
            uint32_t af[2][4];
            ldsm4(af[0], aBase + so + k16 * 32);
            ldsm4(af[1], aBase + so + k16 * 32 + 16 * ROWB);
            uint32_t bf[4][4];
            #pragma unroll
            for (int nj = 0; nj < 4; ++nj)
                ldsm4(bf[nj], bBase + so + k16 * 32 + nj * (16 * ROWB));
            #pragma unroll
            for (int mi = 0; mi < 2; ++mi)
                #pragma unroll
                for (int ni = 0; ni < 8; ++ni)
                    mma16816(acc[mi][ni], af[mi],
                             bf[ni >> 1][(ni & 1) * 2], bf[ni >> 1][(ni & 1) * 2 + 1]);
        }
        __syncthreads();                    // all warps done reading this stage
        if (kt + 2 < nch) ISSUE(kt + 2);    // safe to overwrite it
    }
#undef ISSUE

    // ---- epilogue: + bias, write C ----
    const int g = lane >> 2, t = lane & 3;
    #pragma unroll
    for (int mi = 0; mi < 2; ++mi) {
        float* crow0 = C + (size_t)(Tm * 128 + m0 + mi * 16 + g) * G3 + Tn * 128 + n0;
        float* crow8 = crow0 + 8 * (size_t)G3;
        #pragma unroll
        for (int ni = 0; ni < 8; ++ni) {
            const int col = ni * 8 + 2 * t;
            const float b0 = sbias[n0 + col], b1 = sbias[n0 + col + 1];
            float2 v0 = make_float2(acc[mi][ni][0] + b0, acc[mi][ni][1] + b1);
            float2 v1 = make_float2(acc[mi][ni][2] + b0, acc[mi][ni][3] + b1);
            *(float2*)(crow0 + col) = v0;
            *(float2*)(crow8 + col) = v1;
        }
    }
}

// ---------------- passthrough: out = gather(memory_table / last_update) ----------------
__global__ void passthrough_kernel(const float* __restrict__ mt, const float* __restrict__ lu,
                                   const int* __restrict__ nid,
                                   float* __restrict__ out_mem, float* __restrict__ out_lu)
{
    const int row = blockIdx.x * 4 + (threadIdx.x >> 6);
    const int t   = threadIdx.x & 63;
    const int id  = nid[row];
    const float4 v = *(const float4*)(mt + (size_t)id * DIM + t * 4);
    *(float4*)(out_mem + (size_t)row * DIM + t * 4) = v;
    if (t == 0) out_lu[row] = lu[id];
}

// ---------------- rid[i] = node_ids[to_update[i]] ----------------
__global__ void make_rid_kernel(const int* __restrict__ nid, const int* __restrict__ tu,
                                int* __restrict__ rid)
{
    const int i = blockIdx.x * 256 + threadIdx.x;
    rid[i] = nid[tu[i]];
}

// ---------------- fused GRU gates + LayerNorm + scatter ----------------
__global__ void epilogue_kernel(const float* __restrict__ gx, const float* __restrict__ gh,
                                const float* __restrict__ mt,
                                const float* __restrict__ gamma, const float* __restrict__ beta,
                                const int* __restrict__ rid, const int* __restrict__ tu,
                                const float* __restrict__ ts,
                                float* __restrict__ out_mem, float* __restrict__ out_lu)
{
    const int row = blockIdx.x;
    const int j   = threadIdx.x;     // 256 threads = one per feature
    const size_t base = (size_t)row * G3;

    const float xr = gx[base + j],        hr = gh[base + j];
    const float xz = gx[base + 256 + j],  hz = gh[base + 256 + j];
    const float xn = gx[base + 512 + j],  hn = gh[base + 512 + j];

    const float r = sigm(xr + hr);
    const float z = sigm(xz + hz);
    const float n = tanhf(xn + r * hn);
    const float h = mt[(size_t)rid[row] * DIM + j];
    const float hv = (1.0f - z) * n + z * h;

    float s = hv, s2 = hv * hv;
    #pragma unroll
    for (int o = 16; o > 0; o >>= 1) {
        s  += __shfl_xor_sync(0xffffffffu, s,  o);
        s2 += __shfl_xor_sync(0xffffffffu, s2, o);
    }
    __shared__ float ws[8], ws2[8];
    if ((j & 31) == 0) { ws[j >> 5] = s; ws2[j >> 5] = s2; }
    __syncthreads();
    float tot = 0.f, tot2 = 0.f;
    #pragma unroll
    for (int w = 0; w < 8; ++w) { tot += ws[w]; tot2 += ws2[w]; }
    const float mu  = tot  * (1.0f / 256.0f);
    const float var = tot2 * (1.0f / 256.0f) - mu * mu;
    const float inv = rsqrtf(var + LN_EPS);
    const float o   = (hv - mu) * inv * gamma[j] + beta[j];

    const int orow = tu[row];
    out_mem[(size_t)orow * DIM + j] = o;
    if (j == 0) out_lu[orow] = ts[row];
}

// ---------------- launch ----------------
extern "C" void kernel_launch(void* const* d_in, const int* in_sizes, int n_in,
                              void* d_out, int out_size)
{
    const float* mt    = (const float*)d_in[0];   // memory_table [1e6, 256]
    const float* lu    = (const float*)d_in[1];   // last_update  [1e6]
    const float* Wih   = (const float*)d_in[2];   // [768, 512]
    const float* Whh   = (const float*)d_in[3];   // [768, 256]
    const float* bih   = (const float*)d_in[4];   // [768]
    const float* bhh   = (const float*)d_in[5];   // [768]
    const float* gamma = (const float*)d_in[6];   // [256]
    const float* beta  = (const float*)d_in[7];   // [256]
    const float* msg   = (const float*)d_in[8];   // [131072, 512]
    const float* ts    = (const float*)d_in[9];   // [131072]
    const int*   nid   = (const int*)d_in[10];    // [200000]
    const int*   tu    = (const int*)d_in[11];    // [131072]

    float* out_mem = (float*)d_out;                       // [200000, 256]
    float* out_lu  = out_mem + (size_t)N_GATHER * DIM;    // [200000]

    __nv_bfloat16 *pax, *pah, *pbx, *pbh;
    float *pgx, *pgh; int* prid;
    cudaGetSymbolAddress((void**)&pax,  g_ax);
    cudaGetSymbolAddress((void**)&pah,  g_ah);
    cudaGetSymbolAddress((void**)&pbx,  g_bx);
    cudaGetSymbolAddress((void**)&pbh,  g_bh);
    cudaGetSymbolAddress((void**)&pgx,  g_gx);
    cudaGetSymbolAddress((void**)&pgh,  g_gh);
    cudaGetSymbolAddress((void**)&prid, g_rid);

    cudaFuncSetAttribute(hmma_gemm, cudaFuncAttributeMaxDynamicSharedMemorySize, SMEM_DYN);

    // Launch order puts the big GEMM at launch #6 so ncu (-s 5 -c 1) captures it.
    // 1) row indices for the update subset
    make_rid_kernel<<<M_UPD / 256, 256>>>(nid, tu, prid);

    // 2) bf16 hi/lo conversions: A = [hi|lo] (2K), B = [hi|lo|hi] (3K)
    conv_hilo<<<(M_UPD * (MSG_DIM / 4)) / 256, 256>>>(msg, nullptr, pax, MSG_DIM, 0);
    conv_hilo<<<(M_UPD * (DIM     / 4)) / 256, 256>>>(mt,  prid,    pah, DIM,     0);
    conv_hilo<<<(G3    * (MSG_DIM / 4)) / 256, 256>>>(Wih, nullptr, pbx, MSG_DIM, 1);
    conv_hilo<<<(G3    * (DIM     / 4)) / 256, 256>>>(Whh, nullptr, pbh, DIM,     1);

    // 3) the two tensor-core GEMMs (segsh: log2(K/64) -> 3 for K=512, 2 for K=256)
    dim3 gg(G3 / 128, M_UPD / 128);   // (6, 1024)
    hmma_gemm<<<gg, 256, SMEM_DYN>>>(pax, pbx, bih, pgx, 3);
    hmma_gemm<<<gg, 256, SMEM_DYN>>>(pah, pbh, bhh, pgh, 2);

    // 4) gather passthrough for all rows (updated rows overwritten later)
    passthrough_kernel<<<N_GATHER / 4, 256>>>(mt, lu, nid, out_mem, out_lu);

    // 5) GRU gates + LayerNorm + scatter
    epilogue_kernel<<<M_UPD, 256>>>(pgx, pgh, mt, gamma, beta, prid, tu, ts, out_mem, out_lu);
}

// round 13
// speedup vs baseline: 1.2713x; 1.2713x over previous
#include <cuda_runtime.h>
#include <cuda_bf16.h>
#include <math.h>
#include <stdint.h>

// ---------------- problem constants ----------------
#define N_TOTAL   1000000
#define N_GATHER  200000
#define M_UPD     131072
#define MSG_DIM   512
#define DIM       256
#define G3        768
#define LN_EPS    1e-5f

// ---------------- scratch (static device globals: allocation-free) ----------------
// A operands stored WITHOUT hi duplication: [Ah | Al], row length 2K.
__device__ __nv_bfloat16 g_ax[(size_t)M_UPD * 2 * MSG_DIM];  // 268 MB
__device__ __nv_bfloat16 g_ah[(size_t)M_UPD * 2 * DIM];      // 134 MB
// B operands stored in full logical order: [Bh | Bl | Bh], row length 3K (tiny).
__device__ __nv_bfloat16 g_bx[(size_t)G3 * 3 * MSG_DIM];
__device__ __nv_bfloat16 g_bh[(size_t)G3 * 3 * DIM];
__device__ float g_gx[(size_t)M_UPD * G3];
__device__ float g_gh[(size_t)M_UPD * G3];
__device__ int   g_rid[M_UPD];

// ---------------- helpers ----------------
__device__ __forceinline__ uint32_t smem_u32(const void* p) {
    uint32_t a;
    asm("{ .reg .u64 t; cvta.to.shared.u64 t, %1; cvt.u32.u64 %0, t; }" : "=r"(a) : "l"(p));
    return a;
}
__device__ __forceinline__ void cpa16(uint32_t dst, const void* src) {
    asm volatile("cp.async.cg.shared.global [%0], [%1], 16;" :: "r"(dst), "l"(src) : "memory");
}
__device__ __forceinline__ void ldsm4(uint32_t* r, uint32_t addr) {
    asm volatile("ldmatrix.sync.aligned.m8n8.x4.shared.b16 {%0,%1,%2,%3}, [%4];"
                 : "=r"(r[0]), "=r"(r[1]), "=r"(r[2]), "=r"(r[3]) : "r"(addr));
}
__device__ __forceinline__ void mma16816(float* d, const uint32_t* a, uint32_t b0, uint32_t b1) {
    asm volatile("mma.sync.aligned.m16n8k16.row.col.f32.bf16.bf16.f32 "
                 "{%0,%1,%2,%3}, {%4,%5,%6,%7}, {%8,%9}, {%0,%1,%2,%3};"
                 : "+f"(d[0]), "+f"(d[1]), "+f"(d[2]), "+f"(d[3])
                 : "r"(a[0]), "r"(a[1]), "r"(a[2]), "r"(a[3]), "r"(b0), "r"(b1));
}
__device__ __forceinline__ float sigm(float x) { return 1.0f / (1.0f + expf(-x)); }

// ==================================================================================
// Conversion: X[rows,K] fp32 (optionally row-gathered) -> bf16 hi/lo.
//   bmode=0 (A operand): row = [hi | lo]          (length 2K)
//   bmode=1 (B operand): row = [hi | lo | hi]     (length 3K)
// GEMM pairs segments so sum = Ah*Bh + Ah*Bl + Al*Bh (Al*Bl dropped, ~4e-6 rel).
// ==================================================================================
__global__ void conv_hilo(const float* __restrict__ src, const int* __restrict__ rowidx,
                          __nv_bfloat16* __restrict__ dst, int K, int bmode)
{
    const int q  = blockIdx.x * 256 + threadIdx.x;   // grid sized exactly: rows*K/4 threads
    const int kq = K >> 2;
    const int m  = q / kq;
    const int k  = (q - m * kq) << 2;

    const int srow = rowidx ? rowidx[m] : m;
    const float4 v = *(const float4*)(src + (size_t)srow * K + k);

    const __nv_bfloat16 h0 = __float2bfloat16(v.x);
    const __nv_bfloat16 h1 = __float2bfloat16(v.y);
    const __nv_bfloat16 h2 = __float2bfloat16(v.z);
    const __nv_bfloat16 h3 = __float2bfloat16(v.w);
    const __nv_bfloat16 l0 = __float2bfloat16(v.x - __bfloat162float(h0));
    const __nv_bfloat16 l1 = __float2bfloat16(v.y - __bfloat162float(h1));
    const __nv_bfloat16 l2 = __float2bfloat16(v.z - __bfloat162float(h2));
    const __nv_bfloat16 l3 = __float2bfloat16(v.w - __bfloat162float(h3));

    unsigned long long hq =  (unsigned long long)__bfloat16_as_ushort(h0)
                          | ((unsigned long long)__bfloat16_as_ushort(h1) << 16)
                          | ((unsigned long long)__bfloat16_as_ushort(h2) << 32)
                          | ((unsigned long long)__bfloat16_as_ushort(h3) << 48);
    unsigned long long lq =  (unsigned long long)__bfloat16_as_ushort(l0)
                          | ((unsigned long long)__bfloat16_as_ushort(l1) << 16)
                          | ((unsigned long long)__bfloat16_as_ushort(l2) << 32)
                          | ((unsigned long long)__bfloat16_as_ushort(l3) << 48);

    if (bmode == 0) {
        unsigned long long* drow = (unsigned long long*)(dst + (size_t)m * 2 * K);
        drow[k >> 2]           = hq;
        drow[(K + k) >> 2]     = lq;
    } else {
        unsigned long long* drow = (unsigned long long*)(dst + (size_t)m * 3 * K);
        drow[k >> 2]           = hq;
        drow[(K + k) >> 2]     = lq;
        drow[(2 * K + k) >> 2] = hq;
    }
}

// ==================================================================================
// HMMA GEMM: C[M,768] = A[M,2K](no-dup hi/lo) @ B[768,3K]^T + bias
// Logical K' = 3K in 32-wide chunks; A chunk remapped (seg0,1 -> Ah, seg2 -> Al).
// bf16 mma.sync m16n8k16 (row.col, TN), fp32 accum.
// CTA tile 128x128x32, 8 warps (4M x 2N, warp tile 32x64), 4-stage cp.async ring
// with prefetch distance 3 (the R8 structure that measured 1957us).
// SMEM rows padded to 40 bf16 (80B): conflict-free for cp.async stores and LDSM.
// ==================================================================================
#define STAGES    4
#define STAGE_B   10240u            // 128 rows * 80 bytes
#define SMEM_DYN  (2 * STAGES * STAGE_B)   // A ring + B ring = 81920 B

__global__ __launch_bounds__(256, 2)
void hmma_gemm(const __nv_bfloat16* __restrict__ A, const __nv_bfloat16* __restrict__ B,
               const float* __restrict__ bias, float* __restrict__ C, int s5)
{
    extern __shared__ char dsm[];
    __shared__ float sbias[128];

    const int tid = threadIdx.x, wid = tid >> 5, lane = tid & 31;
    const int Tn = blockIdx.x, Tm = blockIdx.y;
    const int segch   = 1 << s5;          // 32-chunks per K segment (16 for K=512, 8 for K=256)
    const int nchunks = 3 << s5;          // logical chunks (48 / 24)
    const int strideA = 64 << s5;         // 2K elements
    const int strideB = 96 << s5;         // 3K elements

    if (tid < 128) sbias[tid] = bias[Tn * 128 + tid];

    const uint32_t smA = smem_u32(dsm);
    const uint32_t smB = smA + STAGES * STAGE_B;

    // ---- cp.async mapping: 512 16B-chunks per matrix per stage, 2 per thread ----
    const int r = tid >> 2, c = tid & 3;          // row 0..63(+64), 16B col chunk 0..3
    const __nv_bfloat16* aG0 = A + (size_t)(Tm * 128 + r) * strideA + c * 8;
    const __nv_bfloat16* bG0 = B + (size_t)(Tn * 128 + r) * strideB + c * 8;
    const __nv_bfloat16* aG1 = aG0 + (size_t)64 * strideA;
    const __nv_bfloat16* bG1 = bG0 + (size_t)64 * strideB;
    const uint32_t dA0 = smA + r * 80 + c * 16;
    const uint32_t dB0 = smB + r * 80 + c * 16;
    const uint32_t dA1 = dA0 + 64 * 80;
    const uint32_t dB1 = dB0 + 64 * 80;

#define ISSUE(kt)                                                                  \
    do { const int sg_ = (kt) >> s5, c_ = (kt) & (segch - 1);                      \
         const int ach_ = (sg_ == 2) ? (segch + c_) : c_;                          \
         const uint32_t so_ = ((kt) & (STAGES - 1)) * STAGE_B;                     \
         const size_t ao_ = (size_t)ach_ * 32, bo_ = (size_t)(kt) * 32;            \
         cpa16(dA0 + so_, aG0 + ao_); cpa16(dA1 + so_, aG1 + ao_);                 \
         cpa16(dB0 + so_, bG0 + bo_); cpa16(dB1 + so_, bG1 + bo_);                 \
         asm volatile("cp.async.commit_group;" ::: "memory"); } while (0)

    // ---- ldmatrix per-lane base addresses (byte offsets within a stage) ----
    const int wm = wid >> 1, wn = wid & 1;
    const int m0 = wm * 32,  n0 = wn * 64;
    const uint32_t aBase = smA + (m0 + (lane & 15)) * 80 + (lane >> 4) * 16;
    const uint32_t bBase = smB + (n0 + (((lane >> 4) & 1) * 8) + (lane & 7)) * 80
                               + (((lane >> 3) & 1) * 16);

    float acc[2][8][4];
    #pragma unroll
    for (int mi = 0; mi < 2; ++mi)
        #pragma unroll
        for (int ni = 0; ni < 8; ++ni)
            #pragma unroll
            for (int j = 0; j < 4; ++j) acc[mi][ni][j] = 0.f;

    ISSUE(0); ISSUE(1); ISSUE(2);     // nchunks >= 24 always

    for (int kt = 0; kt < nchunks; ++kt) {
        asm volatile("cp.async.wait_group 2;" ::: "memory");
        __syncthreads();
        if (kt + 3 < nchunks) ISSUE(kt + 3);

        const uint32_t so = (kt & (STAGES - 1)) * STAGE_B;
        #pragma unroll
        for (int k16 = 0; k16 < 2; ++k16) {
            uint32_t af[2][4];
            ldsm4(af[0], aBase + so + k16 * 32);
            ldsm4(af[1], aBase + so + k16 * 32 + 16 * 80);
            uint32_t bf[4][4];
            #pragma unroll
            for (int nj = 0; nj < 4; ++nj)
                ldsm4(bf[nj], bBase + so + k16 * 32 + nj * (16 * 80));
            #pragma unroll
            for (int mi = 0; mi < 2; ++mi)
                #pragma unroll
                for (int ni = 0; ni < 8; ++ni)
                    mma16816(acc[mi][ni], af[mi],
                             bf[ni >> 1][(ni & 1) * 2], bf[ni >> 1][(ni & 1) * 2 + 1]);
        }
    }
#undef ISSUE

    // ---- epilogue: + bias, write C ----
    const int g = lane >> 2, t = lane & 3;
    #pragma unroll
    for (int mi = 0; mi < 2; ++mi) {
        float* crow0 = C + (size_t)(Tm * 128 + m0 + mi * 16 + g) * G3 + Tn * 128 + n0;
        float* crow8 = crow0 + 8 * (size_t)G3;
        #pragma unroll
        for (int ni = 0; ni < 8; ++ni) {
            const int col = ni * 8 + 2 * t;
            const float b0 = sbias[n0 + col], b1 = sbias[n0 + col + 1];
            float2 v0 = make_float2(acc[mi][ni][0] + b0, acc[mi][ni][1] + b1);
            float2 v1 = make_float2(acc[mi][ni][2] + b0, acc[mi][ni][3] + b1);
            *(float2*)(crow0 + col) = v0;
            *(float2*)(crow8 + col) = v1;
        }
    }
}

// ---------------- passthrough: out = gather(memory_table / last_update) ----------------
__global__ void passthrough_kernel(const float* __restrict__ mt, const float* __restrict__ lu,
                                   const int* __restrict__ nid,
                                   float* __restrict__ out_mem, float* __restrict__ out_lu)
{
    const int row = blockIdx.x * 4 + (threadIdx.x >> 6);
    const int t   = threadIdx.x & 63;
    const int id  = nid[row];
    const float4 v = *(const float4*)(mt + (size_t)id * DIM + t * 4);
    *(float4*)(out_mem + (size_t)row * DIM + t * 4) = v;
    if (t == 0) out_lu[row] = lu[id];
}

// ---------------- rid[i] = node_ids[to_update[i]] ----------------
__global__ void make_rid_kernel(const int* __restrict__ nid, const int* __restrict__ tu,
                                int* __restrict__ rid)
{
    const int i = blockIdx.x * 256 + threadIdx.x;
    rid[i] = nid[tu[i]];
}

// ---------------- fused GRU gates + LayerNorm + scatter ----------------
__global__ void epilogue_kernel(const float* __restrict__ gx, const float* __restrict__ gh,
                                const float* __restrict__ mt,
                                const float* __restrict__ gamma, const float* __restrict__ beta,
                                const int* __restrict__ rid, const int* __restrict__ tu,
                                const float* __restrict__ ts,
                                float* __restrict__ out_mem, float* __restrict__ out_lu)
{
    const int row = blockIdx.x;
    const int j   = threadIdx.x;     // 256 threads = one per feature
    const size_t base = (size_t)row * G3;

    const float xr = gx[base + j],        hr = gh[base + j];
    const float xz = gx[base + 256 + j],  hz = gh[base + 256 + j];
    const float xn = gx[base + 512 + j],  hn = gh[base + 512 + j];

    const float r = sigm(xr + hr);
    const float z = sigm(xz + hz);
    const float n = tanhf(xn + r * hn);
    const float h = mt[(size_t)rid[row] * DIM + j];
    const float hv = (1.0f - z) * n + z * h;

    float s = hv, s2 = hv * hv;
    #pragma unroll
    for (int o = 16; o > 0; o >>= 1) {
        s  += __shfl_xor_sync(0xffffffffu, s,  o);
        s2 += __shfl_xor_sync(0xffffffffu, s2, o);
    }
    __shared__ float ws[8], ws2[8];
    if ((j & 31) == 0) { ws[j >> 5] = s; ws2[j >> 5] = s2; }
    __syncthreads();
    float tot = 0.f, tot2 = 0.f;
    #pragma unroll
    for (int w = 0; w < 8; ++w) { tot += ws[w]; tot2 += ws2[w]; }
    const float mu  = tot  * (1.0f / 256.0f);
    const float var = tot2 * (1.0f / 256.0f) - mu * mu;
    const float inv = rsqrtf(var + LN_EPS);
    const float o   = (hv - mu) * inv * gamma[j] + beta[j];

    const int orow = tu[row];
    out_mem[(size_t)orow * DIM + j] = o;
    if (j == 0) out_lu[orow] = ts[row];
}

// ---------------- launch ----------------
extern "C" void kernel_launch(void* const* d_in, const int* in_sizes, int n_in,
                              void* d_out, int out_size)
{
    const float* mt    = (const float*)d_in[0];   // memory_table [1e6, 256]
    const float* lu    = (const float*)d_in[1];   // last_update  [1e6]
    const float* Wih   = (const float*)d_in[2];   // [768, 512]
    const float* Whh   = (const float*)d_in[3];   // [768, 256]
    const float* bih   = (const float*)d_in[4];   // [768]
    const float* bhh   = (const float*)d_in[5];   // [768]
    const float* gamma = (const float*)d_in[6];   // [256]
    const float* beta  = (const float*)d_in[7];   // [256]
    const float* msg   = (const float*)d_in[8];   // [131072, 512]
    const float* ts    = (const float*)d_in[9];   // [131072]
    const int*   nid   = (const int*)d_in[10];    // [200000]
    const int*   tu    = (const int*)d_in[11];    // [131072]

    float* out_mem = (float*)d_out;                       // [200000, 256]
    float* out_lu  = out_mem + (size_t)N_GATHER * DIM;    // [200000]

    __nv_bfloat16 *pax, *pah, *pbx, *pbh;
    float *pgx, *pgh; int* prid;
    cudaGetSymbolAddress((void**)&pax,  g_ax);
    cudaGetSymbolAddress((void**)&pah,  g_ah);
    cudaGetSymbolAddress((void**)&pbx,  g_bx);
    cudaGetSymbolAddress((void**)&pbh,  g_bh);
    cudaGetSymbolAddress((void**)&pgx,  g_gx);
    cudaGetSymbolAddress((void**)&pgh,  g_gh);
    cudaGetSymbolAddress((void**)&prid, g_rid);

    cudaFuncSetAttribute(hmma_gemm, cudaFuncAttributeMaxDynamicSharedMemorySize, SMEM_DYN);

    // 1) row indices for the update subset
    make_rid_kernel<<<M_UPD / 256, 256>>>(nid, tu, prid);

    // 2) bf16 hi/lo conversions: A = [hi|lo] (2K), B = [hi|lo|hi] (3K)
    conv_hilo<<<(M_UPD * (MSG_DIM / 4)) / 256, 256>>>(msg, nullptr, pax, MSG_DIM, 0);
    conv_hilo<<<(M_UPD * (DIM     / 4)) / 256, 256>>>(mt,  prid,    pah, DIM,     0);
    conv_hilo<<<(G3    * (MSG_DIM / 4)) / 256, 256>>>(Wih, nullptr, pbx, MSG_DIM, 1);
    conv_hilo<<<(G3    * (DIM     / 4)) / 256, 256>>>(Whh, nullptr, pbh, DIM,     1);

    // 3) the two tensor-core GEMMs (s5 = log2(K/32): 4 for K=512, 3 for K=256)
    dim3 gg(G3 / 128, M_UPD / 128);   // (6, 1024)
    hmma_gemm<<<gg, 256, SMEM_DYN>>>(pax, pbx, bih, pgx, 4);
    hmma_gemm<<<gg, 256, SMEM_DYN>>>(pah, pbh, bhh, pgh, 3);

    // 4) gather passthrough for all rows (updated rows overwritten later)
    passthrough_kernel<<<N_GATHER / 4, 256>>>(mt, lu, nid, out_mem, out_lu);

    // 5) GRU gates + LayerNorm + scatter
    epilogue_kernel<<<M_UPD, 256>>>(pgx, pgh, mt, gamma, beta, prid, tu, ts, out_mem, out_lu);
}

// round 17
// speedup vs baseline: 1.3733x; 1.0802x over previous
#include <cuda_runtime.h>
#include <cuda_bf16.h>
#include <math.h>
#include <stdint.h>

// ---------------- problem constants ----------------
#define N_TOTAL   1000000
#define N_GATHER  200000
#define M_UPD     131072
#define MSG_DIM   512
#define DIM       256
#define G3        768
#define LN_EPS    1e-5f

// ---------------- scratch (static device globals: allocation-free) ----------------
// A operands stored WITHOUT hi duplication: [Ah | Al], row length 2K.
__device__ __nv_bfloat16 g_ax[(size_t)M_UPD * 2 * MSG_DIM];  // 268 MB
__device__ __nv_bfloat16 g_ah[(size_t)M_UPD * 2 * DIM];      // 134 MB
// B operands stored in full logical order: [Bh | Bl | Bh], row length 3K (tiny).
__device__ __nv_bfloat16 g_bx[(size_t)G3 * 3 * MSG_DIM];
__device__ __nv_bfloat16 g_bh[(size_t)G3 * 3 * DIM];
__device__ float g_gx[(size_t)M_UPD * G3];
__device__ float g_gh[(size_t)M_UPD * G3];
__device__ int   g_rid[M_UPD];

// ---------------- helpers ----------------
__device__ __forceinline__ uint32_t smem_u32(const void* p) {
    uint32_t a;
    asm("{ .reg .u64 t; cvta.to.shared.u64 t, %1; cvt.u32.u64 %0, t; }" : "=r"(a) : "l"(p));
    return a;
}
__device__ __forceinline__ void cpa16(uint32_t dst, const void* src) {
    asm volatile("cp.async.cg.shared.global [%0], [%1], 16;" :: "r"(dst), "l"(src) : "memory");
}
__device__ __forceinline__ void ldsm4(uint32_t* r, uint32_t addr) {
    asm volatile("ldmatrix.sync.aligned.m8n8.x4.shared.b16 {%0,%1,%2,%3}, [%4];"
                 : "=r"(r[0]), "=r"(r[1]), "=r"(r[2]), "=r"(r[3]) : "r"(addr));
}
__device__ __forceinline__ void mma16816(float* d, const uint32_t* a, uint32_t b0, uint32_t b1) {
    asm volatile("mma.sync.aligned.m16n8k16.row.col.f32.bf16.bf16.f32 "
                 "{%0,%1,%2,%3}, {%4,%5,%6,%7}, {%8,%9}, {%0,%1,%2,%3};"
                 : "+f"(d[0]), "+f"(d[1]), "+f"(d[2]), "+f"(d[3])
                 : "r"(a[0]), "r"(a[1]), "r"(a[2]), "r"(a[3]), "r"(b0), "r"(b1));
}
__device__ __forceinline__ float sigm(float x) { return 1.0f / (1.0f + expf(-x)); }

// ==================================================================================
// Conversion: X[rows,K] fp32 (optionally row-gathered) -> bf16 hi/lo.
//   bmode=0 (A operand): row = [hi | lo]          (length 2K)
//   bmode=1 (B operand): row = [hi | lo | hi]     (length 3K)
// GEMM pairs segments so sum = Ah*Bh + Ah*Bl + Al*Bh (Al*Bl dropped, ~4e-6 rel).
// ==================================================================================
__global__ void conv_hilo(const float* __restrict__ src, const int* __restrict__ rowidx,
                          __nv_bfloat16* __restrict__ dst, int K, int bmode)
{
    const int q  = blockIdx.x * 256 + threadIdx.x;   // grid sized exactly: rows*K/4 threads
    const int kq = K >> 2;
    const int m  = q / kq;
    const int k  = (q - m * kq) << 2;

    const int srow = rowidx ? rowidx[m] : m;
    const float4 v = *(const float4*)(src + (size_t)srow * K + k);

    const __nv_bfloat16 h0 = __float2bfloat16(v.x);
    const __nv_bfloat16 h1 = __float2bfloat16(v.y);
    const __nv_bfloat16 h2 = __float2bfloat16(v.z);
    const __nv_bfloat16 h3 = __float2bfloat16(v.w);
    const __nv_bfloat16 l0 = __float2bfloat16(v.x - __bfloat162float(h0));
    const __nv_bfloat16 l1 = __float2bfloat16(v.y - __bfloat162float(h1));
    const __nv_bfloat16 l2 = __float2bfloat16(v.z - __bfloat162float(h2));
    const __nv_bfloat16 l3 = __float2bfloat16(v.w - __bfloat162float(h3));

    unsigned long long hq =  (unsigned long long)__bfloat16_as_ushort(h0)
                          | ((unsigned long long)__bfloat16_as_ushort(h1) << 16)
                          | ((unsigned long long)__bfloat16_as_ushort(h2) << 32)
                          | ((unsigned long long)__bfloat16_as_ushort(h3) << 48);
    unsigned long long lq =  (unsigned long long)__bfloat16_as_ushort(l0)
                          | ((unsigned long long)__bfloat16_as_ushort(l1) << 16)
                          | ((unsigned long long)__bfloat16_as_ushort(l2) << 32)
                          | ((unsigned long long)__bfloat16_as_ushort(l3) << 48);

    if (bmode == 0) {
        unsigned long long* drow = (unsigned long long*)(dst + (size_t)m * 2 * K);
        drow[k >> 2]           = hq;
        drow[(K + k) >> 2]     = lq;
    } else {
        unsigned long long* drow = (unsigned long long*)(dst + (size_t)m * 3 * K);
        drow[k >> 2]           = hq;
        drow[(K + k) >> 2]     = lq;
        drow[(2 * K + k) >> 2] = hq;
    }
}

// ==================================================================================
// HMMA GEMM: C[M,768] = A[M,2K](no-dup hi/lo) @ B[768,3K]^T + bias
// Logical K' = 3K in 32-wide chunks; A chunk remapped (seg0,1 -> Ah, seg2 -> Al).
// bf16 mma.sync m16n8k16 (row.col, TN), fp32 accum.
// CTA tile 128x128x32, FOUR warps (2M x 2N, warp tile 64x64) -> LDSM replication
// A x2 / B x2 (was x2/x4): smem traffic 48->32 KB per chunk, LDSM:MMA 0.25.
// 4-stage cp.async ring, prefetch distance 3; exact tail wait.
// SMEM rows padded to 40 bf16 (80B): conflict-free for cp.async stores and LDSM.
// ==================================================================================
#define STAGES    4
#define STAGE_B   10240u            // 128 rows * 80 bytes
#define SMEM_DYN  (2 * STAGES * STAGE_B)   // A ring + B ring = 81920 B

__global__ __launch_bounds__(128, 2)
void hmma_gemm(const __nv_bfloat16* __restrict__ A, const __nv_bfloat16* __restrict__ B,
               const float* __restrict__ bias, float* __restrict__ C, int s5)
{
    extern __shared__ char dsm[];
    __shared__ float sbias[128];

    const int tid = threadIdx.x, wid = tid >> 5, lane = tid & 31;
    const int Tn = blockIdx.x, Tm = blockIdx.y;
    const int segch   = 1 << s5;          // 32-chunks per K segment (16 for K=512, 8 for K=256)
    const int nchunks = 3 << s5;          // logical chunks (48 / 24)
    const int strideA = 64 << s5;         // 2K elements
    const int strideB = 96 << s5;         // 3K elements

    sbias[tid] = bias[Tn * 128 + tid];

    const uint32_t smA = smem_u32(dsm);
    const uint32_t smB = smA + STAGES * STAGE_B;

    // ---- cp.async mapping: 128 threads, 4 rows each per matrix (16B per row) ----
    const int r0 = tid >> 2, c = tid & 3;         // rows r0+32i, 16B col chunk c
    const __nv_bfloat16* aG[4]; const __nv_bfloat16* bG[4];
    uint32_t dA[4], dB[4];
    #pragma unroll
    for (int i = 0; i < 4; ++i) {
        const int row = r0 + 32 * i;
        aG[i] = A + (size_t)(Tm * 128 + row) * strideA + c * 8;
        bG[i] = B + (size_t)(Tn * 128 + row) * strideB + c * 8;
        dA[i] = smA + row * 80 + c * 16;
        dB[i] = smB + row * 80 + c * 16;
    }

#define ISSUE(kt)                                                                  \
    do { const int sg_ = (kt) >> s5, c_ = (kt) & (segch - 1);                      \
         const int ach_ = (sg_ == 2) ? (segch + c_) : c_;                          \
         const uint32_t so_ = ((kt) & (STAGES - 1)) * STAGE_B;                     \
         const size_t ao_ = (size_t)ach_ * 32, bo_ = (size_t)(kt) * 32;            \
         _Pragma("unroll")                                                         \
         for (int i_ = 0; i_ < 4; ++i_) { cpa16(dA[i_] + so_, aG[i_] + ao_);       \
                                          cpa16(dB[i_] + so_, bG[i_] + bo_); }     \
         asm volatile("cp.async.commit_group;" ::: "memory"); } while (0)

    // ---- ldmatrix per-lane base addresses (byte offsets within a stage) ----
    const int wm = wid >> 1, wn = wid & 1;
    const int m0 = wm * 64, n0 = wn * 64;
    uint32_t aB[4], bB[4];
    #pragma unroll
    for (int mt = 0; mt < 4; ++mt)
        aB[mt] = smA + (m0 + mt * 16 + (lane & 15)) * 80 + (lane >> 4) * 16;
    #pragma unroll
    for (int nj = 0; nj < 4; ++nj)
        bB[nj] = smB + (n0 + nj * 16 + (((lane >> 4) & 1) * 8) + (lane & 7)) * 80
                     + (((lane >> 3) & 1) * 16);

    float acc[4][8][4];
    #pragma unroll
    for (int mi = 0; mi < 4; ++mi)
        #pragma unroll
        for (int ni = 0; ni < 8; ++ni)
            #pragma unroll
            for (int j = 0; j < 4; ++j) acc[mi][ni][j] = 0.f;

    ISSUE(0); ISSUE(1); ISSUE(2);     // nchunks >= 24 always

    for (int kt = 0; kt < nchunks; ++kt) {
        // exact wait: while still issuing, 2 groups may remain in flight; at the
        // tail drain everything (group kt completion is then guaranteed).
        if (kt + 3 < nchunks) asm volatile("cp.async.wait_group 2;" ::: "memory");
        else                  asm volatile("cp.async.wait_group 0;" ::: "memory");
        __syncthreads();
        if (kt + 3 < nchunks) ISSUE(kt + 3);

        const uint32_t so = (kt & (STAGES - 1)) * STAGE_B;
        #pragma unroll
        for (int k16 = 0; k16 < 2; ++k16) {
            uint32_t af[4][4], bf[4][4];
            #pragma unroll
            for (int mt = 0; mt < 4; ++mt) ldsm4(af[mt], aB[mt] + so + k16 * 32);
            #pragma unroll
            for (int nj = 0; nj < 4; ++nj) ldsm4(bf[nj], bB[nj] + so + k16 * 32);
            #pragma unroll
            for (int mi = 0; mi < 4; ++mi)
                #pragma unroll
                for (int ni = 0; ni < 8; ++ni)
                    mma16816(acc[mi][ni], af[mi],
                             bf[ni >> 1][(ni & 1) * 2], bf[ni >> 1][(ni & 1) * 2 + 1]);
        }
    }
#undef ISSUE

    // ---- epilogue: + bias, write C ----
    const int g = lane >> 2, t = lane & 3;
    #pragma unroll
    for (int mi = 0; mi < 4; ++mi) {
        float* crow0 = C + (size_t)(Tm * 128 + m0 + mi * 16 + g) * G3 + Tn * 128 + n0;
        float* crow8 = crow0 + 8 * (size_t)G3;
        #pragma unroll
        for (int ni = 0; ni < 8; ++ni) {
            const int col = ni * 8 + 2 * t;
            const float b0 = sbias[n0 + col], b1 = sbias[n0 + col + 1];
            float2 v0 = make_float2(acc[mi][ni][0] + b0, acc[mi][ni][1] + b1);
            float2 v1 = make_float2(acc[mi][ni][2] + b0, acc[mi][ni][3] + b1);
            *(float2*)(crow0 + col) = v0;
            *(float2*)(crow8 + col) = v1;
        }
    }
}

// ---------------- passthrough: out = gather(memory_table / last_update) ----------------
__global__ void passthrough_kernel(const float* __restrict__ mt, const float* __restrict__ lu,
                                   const int* __restrict__ nid,
                                   float* __restrict__ out_mem, float* __restrict__ out_lu)
{
    const int row = blockIdx.x * 4 + (threadIdx.x >> 6);
    const int t   = threadIdx.x & 63;
    const int id  = nid[row];
    const float4 v = *(const float4*)(mt + (size_t)id * DIM + t * 4);
    *(float4*)(out_mem + (size_t)row * DIM + t * 4) = v;
    if (t == 0) out_lu[row] = lu[id];
}

// ---------------- rid[i] = node_ids[to_update[i]] ----------------
__global__ void make_rid_kernel(const int* __restrict__ nid, const int* __restrict__ tu,
                                int* __restrict__ rid)
{
    const int i = blockIdx.x * 256 + threadIdx.x;
    rid[i] = nid[tu[i]];
}

// ---------------- fused GRU gates + LayerNorm + scatter ----------------
__global__ void epilogue_kernel(const float* __restrict__ gx, const float* __restrict__ gh,
                                const float* __restrict__ mt,
                                const float* __restrict__ gamma, const float* __restrict__ beta,
                                const int* __restrict__ rid, const int* __restrict__ tu,
                                const float* __restrict__ ts,
                                float* __restrict__ out_mem, float* __restrict__ out_lu)
{
    const int row = blockIdx.x;
    const int j   = threadIdx.x;     // 256 threads = one per feature
    const size_t base = (size_t)row * G3;

    const float xr = gx[base + j],        hr = gh[base + j];
    const float xz = gx[base + 256 + j],  hz = gh[base + 256 + j];
    const float xn = gx[base + 512 + j],  hn = gh[base + 512 + j];

    const float r = sigm(xr + hr);
    const float z = sigm(xz + hz);
    const float n = tanhf(xn + r * hn);
    const float h = mt[(size_t)rid[row] * DIM + j];
    const float hv = (1.0f - z) * n + z * h;

    float s = hv, s2 = hv * hv;
    #pragma unroll
    for (int o = 16; o > 0; o >>= 1) {
        s  += __shfl_xor_sync(0xffffffffu, s,  o);
        s2 += __shfl_xor_sync(0xffffffffu, s2, o);
    }
    __shared__ float ws[8], ws2[8];
    if ((j & 31) == 0) { ws[j >> 5] = s; ws2[j >> 5] = s2; }
    __syncthreads();
    float tot = 0.f, tot2 = 0.f;
    #pragma unroll
    for (int w = 0; w < 8; ++w) { tot += ws[w]; tot2 += ws2[w]; }
    const float mu  = tot  * (1.0f / 256.0f);
    const float var = tot2 * (1.0f / 256.0f) - mu * mu;
    const float inv = rsqrtf(var + LN_EPS);
    const float o   = (hv - mu) * inv * gamma[j] + beta[j];

    const int orow = tu[row];
    out_mem[(size_t)orow * DIM + j] = o;
    if (j == 0) out_lu[orow] = ts[row];
}

// ---------------- launch ----------------
extern "C" void kernel_launch(void* const* d_in, const int* in_sizes, int n_in,
                              void* d_out, int out_size)
{
    const float* mt    = (const float*)d_in[0];   // memory_table [1e6, 256]
    const float* lu    = (const float*)d_in[1];   // last_update  [1e6]
    const float* Wih   = (const float*)d_in[2];   // [768, 512]
    const float* Whh   = (const float*)d_in[3];   // [768, 256]
    const float* bih   = (const float*)d_in[4];   // [768]
    const float* bhh   = (const float*)d_in[5];   // [768]
    const float* gamma = (const float*)d_in[6];   // [256]
    const float* beta  = (const float*)d_in[7];   // [256]
    const float* msg   = (const float*)d_in[8];   // [131072, 512]
    const float* ts    = (const float*)d_in[9];   // [131072]
    const int*   nid   = (const int*)d_in[10];    // [200000]
    const int*   tu    = (const int*)d_in[11];    // [131072]

    float* out_mem = (float*)d_out;                       // [200000, 256]
    float* out_lu  = out_mem + (size_t)N_GATHER * DIM;    // [200000]

    __nv_bfloat16 *pax, *pah, *pbx, *pbh;
    float *pgx, *pgh; int* prid;
    cudaGetSymbolAddress((void**)&pax,  g_ax);
    cudaGetSymbolAddress((void**)&pah,  g_ah);
    cudaGetSymbolAddress((void**)&pbx,  g_bx);
    cudaGetSymbolAddress((void**)&pbh,  g_bh);
    cudaGetSymbolAddress((void**)&pgx,  g_gx);
    cudaGetSymbolAddress((void**)&pgh,  g_gh);
    cudaGetSymbolAddress((void**)&prid, g_rid);

    cudaFuncSetAttribute(hmma_gemm, cudaFuncAttributeMaxDynamicSharedMemorySize, SMEM_DYN);

    dim3 gg(G3 / 128, M_UPD / 128);   // (6, 1024)

    // Launch order chosen so the big gx GEMM sits at the stream position ncu
    // sampled in prior rounds (#4), while respecting dependencies.
    make_rid_kernel<<<M_UPD / 256, 256>>>(nid, tu, prid);                          // 1
    conv_hilo<<<(M_UPD * (MSG_DIM / 4)) / 256, 256>>>(msg, nullptr, pax, MSG_DIM, 0); // 2
    conv_hilo<<<(G3    * (MSG_DIM / 4)) / 256, 256>>>(Wih, nullptr, pbx, MSG_DIM, 1); // 3
    hmma_gemm<<<gg, 128, SMEM_DYN>>>(pax, pbx, bih, pgx, 4);                       // 4  <- profile target
    conv_hilo<<<(M_UPD * (DIM     / 4)) / 256, 256>>>(mt,  prid,    pah, DIM,     0); // 5
    conv_hilo<<<(G3    * (DIM     / 4)) / 256, 256>>>(Whh, nullptr, pbh, DIM,     1); // 6
    hmma_gemm<<<gg, 128, SMEM_DYN>>>(pah, pbh, bhh, pgh, 3);                       // 7
    passthrough_kernel<<<N_GATHER / 4, 256>>>(mt, lu, nid, out_mem, out_lu);       // 8
    epilogue_kernel<<<M_UPD, 256>>>(pgx, pgh, mt, gamma, beta, prid, tu, ts, out_mem, out_lu); // 9
}